// round 1
// baseline (speedup 1.0000x reference)
#include <cuda_runtime.h>
#include <math.h>

#define N_NODES 100000
#define E_EDGES 400000
#define ND 128
#define ED 64
#define HD 128
#define LN_EPS 1e-5f

// Scratch for per-node aggregated messages (allocation-free rule: __device__ global)
__device__ float g_agg[(size_t)N_NODES * HD];

__global__ void zero_agg_kernel() {
    float4* p = reinterpret_cast<float4*>(g_agg);
    const int n4 = N_NODES * HD / 4;
    for (int i = blockIdx.x * blockDim.x + threadIdx.x; i < n4;
         i += gridDim.x * blockDim.x)
        p[i] = make_float4(0.f, 0.f, 0.f, 0.f);
}

// ---------------------------------------------------------------------------
// Message kernel: per block of 64 edges
//   X[64][320] = [nf[src] | nf[tgt] | ef]       (gathered in 16-wide K chunks)
//   H  = relu(LN(X @ w1 + b1))                  (GEMM1, 4x8 reg tile/thread)
//   M  = H @ w2 + b2                            (GEMM2)
//   atomicAdd into g_agg[tgt]
// 256 threads: trow=tid>>4 (16), tcol=tid&15 (16); rows trow*4+i, cols tcol+16*j
// ---------------------------------------------------------------------------
__global__ __launch_bounds__(256) void msg_kernel(
    const float* __restrict__ nf, const float* __restrict__ ef,
    const int* __restrict__ eidx,
    const float* __restrict__ w1, const float* __restrict__ b1,
    const float* __restrict__ g1, const float* __restrict__ be1,
    const float* __restrict__ w2, const float* __restrict__ b2)
{
    __shared__ float Xs[64][20];    // 16-col chunk, padded (stride 20)
    __shared__ float Ws[16][128];   // weight K-chunk
    __shared__ float Hs[64][132];   // hidden, padded (stride 132)
    __shared__ int   sSrc[64], sTgt[64];

    const int tid  = threadIdx.x;
    const long eBase = (long)blockIdx.x * 64;

    if (tid < 64) {
        long e = eBase + tid;
        int s, t;
        if (e < E_EDGES) { s = eidx[e]; t = eidx[E_EDGES + e]; }
        else { long e2 = e - E_EDGES; s = eidx[E_EDGES + e2]; t = eidx[e2]; }
        sSrc[tid] = s; sTgt[tid] = t;
    }

    const int trow = tid >> 4, tcol = tid & 15;
    const int r0 = trow * 4;
    // loader mapping: one float4 of one row per thread per chunk
    const int lr  = tid >> 2;       // 0..63
    const int lc4 = tid & 3;        // 0..3  (16 floats per row-chunk)
    const long eL  = eBase + lr;
    const long efRow = (eL < E_EDGES) ? eL : eL - E_EDGES;

    float acc[4][8];
    #pragma unroll
    for (int j = 0; j < 8; j++) {
        float bv = b1[tcol + 16 * j];
        #pragma unroll
        for (int i = 0; i < 4; i++) acc[i][j] = bv;
    }
    __syncthreads();   // sSrc/sTgt visible

    // ---- GEMM1: K = 320 in chunks of 16 ----
    for (int kc = 0; kc < 2 * ND + ED; kc += 16) {
        const float* srcp;
        if (kc < ND)            srcp = nf + (long)sSrc[lr] * ND + kc;
        else if (kc < 2 * ND)   srcp = nf + (long)sTgt[lr] * ND + (kc - ND);
        else                    srcp = ef + efRow * ED + (kc - 2 * ND);
        float4 xv = *reinterpret_cast<const float4*>(srcp + lc4 * 4);

        // weights: 16x128 = 512 float4, 2 per thread
        float4 wv0, wv1;
        {
            int i0 = tid,        r_ = i0 >> 5, c_ = i0 & 31;
            wv0 = *reinterpret_cast<const float4*>(w1 + (long)(kc + r_) * HD + c_ * 4);
            int i1 = tid + 256;  r_ = i1 >> 5; c_ = i1 & 31;
            wv1 = *reinterpret_cast<const float4*>(w1 + (long)(kc + r_) * HD + c_ * 4);
        }
        __syncthreads();   // previous chunk's compute done
        *reinterpret_cast<float4*>(&Xs[lr][lc4 * 4]) = xv;
        { int i0 = tid;       *reinterpret_cast<float4*>(&Ws[i0 >> 5][(i0 & 31) * 4]) = wv0; }
        { int i1 = tid + 256; *reinterpret_cast<float4*>(&Ws[i1 >> 5][(i1 & 31) * 4]) = wv1; }
        __syncthreads();

        #pragma unroll
        for (int k = 0; k < 16; k++) {
            float xr[4], wr[8];
            #pragma unroll
            for (int i = 0; i < 4; i++) xr[i] = Xs[r0 + i][k];
            #pragma unroll
            for (int j = 0; j < 8; j++) wr[j] = Ws[k][tcol + 16 * j];
            #pragma unroll
            for (int i = 0; i < 4; i++)
                #pragma unroll
                for (int j = 0; j < 8; j++)
                    acc[i][j] = fmaf(xr[i], wr[j], acc[i][j]);
        }
    }

    // ---- LayerNorm + ReLU (row spread over 16 lanes, 8 vals each) ----
    #pragma unroll
    for (int i = 0; i < 4; i++) {
        float s = 0.f, ss = 0.f;
        #pragma unroll
        for (int j = 0; j < 8; j++) { s += acc[i][j]; ss += acc[i][j] * acc[i][j]; }
        #pragma unroll
        for (int o = 8; o >= 1; o >>= 1) {
            s  += __shfl_xor_sync(0xffffffffu, s,  o);
            ss += __shfl_xor_sync(0xffffffffu, ss, o);
        }
        float mean = s * (1.0f / HD);
        float var  = ss * (1.0f / HD) - mean * mean;
        float rstd = rsqrtf(var + LN_EPS);
        #pragma unroll
        for (int j = 0; j < 8; j++) {
            int c = tcol + 16 * j;
            float h = (acc[i][j] - mean) * rstd * g1[c] + be1[c];
            Hs[r0 + i][c] = fmaxf(h, 0.f);
        }
    }

    // ---- GEMM2: K = 128 in chunks of 16 ----
    float acc2[4][8];
    #pragma unroll
    for (int j = 0; j < 8; j++) {
        float bv = b2[tcol + 16 * j];
        #pragma unroll
        for (int i = 0; i < 4; i++) acc2[i][j] = bv;
    }
    for (int kc = 0; kc < HD; kc += 16) {
        float4 wv0, wv1;
        {
            int i0 = tid,        r_ = i0 >> 5, c_ = i0 & 31;
            wv0 = *reinterpret_cast<const float4*>(w2 + (long)(kc + r_) * HD + c_ * 4);
            int i1 = tid + 256;  r_ = i1 >> 5; c_ = i1 & 31;
            wv1 = *reinterpret_cast<const float4*>(w2 + (long)(kc + r_) * HD + c_ * 4);
        }
        __syncthreads();
        { int i0 = tid;       *reinterpret_cast<float4*>(&Ws[i0 >> 5][(i0 & 31) * 4]) = wv0; }
        { int i1 = tid + 256; *reinterpret_cast<float4*>(&Ws[i1 >> 5][(i1 & 31) * 4]) = wv1; }
        __syncthreads();
        #pragma unroll
        for (int k = 0; k < 16; k++) {
            float xr[4], wr[8];
            #pragma unroll
            for (int i = 0; i < 4; i++) xr[i] = Hs[r0 + i][kc + k];
            #pragma unroll
            for (int j = 0; j < 8; j++) wr[j] = Ws[k][tcol + 16 * j];
            #pragma unroll
            for (int i = 0; i < 4; i++)
                #pragma unroll
                for (int j = 0; j < 8; j++)
                    acc2[i][j] = fmaf(xr[i], wr[j], acc2[i][j]);
        }
    }

    // ---- scatter-add ----
    #pragma unroll
    for (int i = 0; i < 4; i++) {
        float* dst = g_agg + (long)sTgt[r0 + i] * HD;
        #pragma unroll
        for (int j = 0; j < 8; j++)
            atomicAdd(dst + tcol + 16 * j, acc2[i][j]);
    }
}

// ---------------------------------------------------------------------------
// Update kernel: per block of 64 nodes
//   U[64][256] = [nf | agg];  out = nf + (relu(LN(U@uw1+ub1)) @ uw2 + ub2)
// ---------------------------------------------------------------------------
__global__ __launch_bounds__(256) void upd_kernel(
    const float* __restrict__ nf,
    const float* __restrict__ uw1, const float* __restrict__ ub1,
    const float* __restrict__ g2, const float* __restrict__ be2,
    const float* __restrict__ uw2, const float* __restrict__ ub2,
    float* __restrict__ out)
{
    __shared__ float Xs[64][20];
    __shared__ float Ws[16][128];
    __shared__ float Hs[64][132];

    const int tid  = threadIdx.x;
    const long nBase = (long)blockIdx.x * 64;

    const int trow = tid >> 4, tcol = tid & 15;
    const int r0 = trow * 4;
    const int lr  = tid >> 2;
    const int lc4 = tid & 3;
    long rowL = nBase + lr;
    if (rowL >= N_NODES) rowL = N_NODES - 1;   // clamp loads; stores guarded

    float acc[4][8];
    #pragma unroll
    for (int j = 0; j < 8; j++) {
        float bv = ub1[tcol + 16 * j];
        #pragma unroll
        for (int i = 0; i < 4; i++) acc[i][j] = bv;
    }

    // ---- GEMM1: K = 256 in chunks of 16 ----
    for (int kc = 0; kc < ND + HD; kc += 16) {
        const float* srcp = (kc < ND) ? (nf + rowL * ND + kc)
                                      : (g_agg + rowL * HD + (kc - ND));
        float4 xv = *reinterpret_cast<const float4*>(srcp + lc4 * 4);
        float4 wv0, wv1;
        {
            int i0 = tid,        r_ = i0 >> 5, c_ = i0 & 31;
            wv0 = *reinterpret_cast<const float4*>(uw1 + (long)(kc + r_) * HD + c_ * 4);
            int i1 = tid + 256;  r_ = i1 >> 5; c_ = i1 & 31;
            wv1 = *reinterpret_cast<const float4*>(uw1 + (long)(kc + r_) * HD + c_ * 4);
        }
        __syncthreads();
        *reinterpret_cast<float4*>(&Xs[lr][lc4 * 4]) = xv;
        { int i0 = tid;       *reinterpret_cast<float4*>(&Ws[i0 >> 5][(i0 & 31) * 4]) = wv0; }
        { int i1 = tid + 256; *reinterpret_cast<float4*>(&Ws[i1 >> 5][(i1 & 31) * 4]) = wv1; }
        __syncthreads();
        #pragma unroll
        for (int k = 0; k < 16; k++) {
            float xr[4], wr[8];
            #pragma unroll
            for (int i = 0; i < 4; i++) xr[i] = Xs[r0 + i][k];
            #pragma unroll
            for (int j = 0; j < 8; j++) wr[j] = Ws[k][tcol + 16 * j];
            #pragma unroll
            for (int i = 0; i < 4; i++)
                #pragma unroll
                for (int j = 0; j < 8; j++)
                    acc[i][j] = fmaf(xr[i], wr[j], acc[i][j]);
        }
    }

    // ---- LN + ReLU ----
    #pragma unroll
    for (int i = 0; i < 4; i++) {
        float s = 0.f, ss = 0.f;
        #pragma unroll
        for (int j = 0; j < 8; j++) { s += acc[i][j]; ss += acc[i][j] * acc[i][j]; }
        #pragma unroll
        for (int o = 8; o >= 1; o >>= 1) {
            s  += __shfl_xor_sync(0xffffffffu, s,  o);
            ss += __shfl_xor_sync(0xffffffffu, ss, o);
        }
        float mean = s * (1.0f / HD);
        float var  = ss * (1.0f / HD) - mean * mean;
        float rstd = rsqrtf(var + LN_EPS);
        #pragma unroll
        for (int j = 0; j < 8; j++) {
            int c = tcol + 16 * j;
            float h = (acc[i][j] - mean) * rstd * g2[c] + be2[c];
            Hs[r0 + i][c] = fmaxf(h, 0.f);
        }
    }

    // ---- GEMM2 ----
    float acc2[4][8];
    #pragma unroll
    for (int j = 0; j < 8; j++) {
        float bv = ub2[tcol + 16 * j];
        #pragma unroll
        for (int i = 0; i < 4; i++) acc2[i][j] = bv;
    }
    for (int kc = 0; kc < HD; kc += 16) {
        float4 wv0, wv1;
        {
            int i0 = tid,        r_ = i0 >> 5, c_ = i0 & 31;
            wv0 = *reinterpret_cast<const float4*>(uw2 + (long)(kc + r_) * HD + c_ * 4);
            int i1 = tid + 256;  r_ = i1 >> 5; c_ = i1 & 31;
            wv1 = *reinterpret_cast<const float4*>(uw2 + (long)(kc + r_) * HD + c_ * 4);
        }
        __syncthreads();
        { int i0 = tid;       *reinterpret_cast<float4*>(&Ws[i0 >> 5][(i0 & 31) * 4]) = wv0; }
        { int i1 = tid + 256; *reinterpret_cast<float4*>(&Ws[i1 >> 5][(i1 & 31) * 4]) = wv1; }
        __syncthreads();
        #pragma unroll
        for (int k = 0; k < 16; k++) {
            float xr[4], wr[8];
            #pragma unroll
            for (int i = 0; i < 4; i++) xr[i] = Hs[r0 + i][kc + k];
            #pragma unroll
            for (int j = 0; j < 8; j++) wr[j] = Ws[k][tcol + 16 * j];
            #pragma unroll
            for (int i = 0; i < 4; i++)
                #pragma unroll
                for (int j = 0; j < 8; j++)
                    acc2[i][j] = fmaf(xr[i], wr[j], acc2[i][j]);
        }
    }

    // ---- residual + store (guarded) ----
    #pragma unroll
    for (int i = 0; i < 4; i++) {
        long row = nBase + r0 + i;
        if (row < N_NODES) {
            #pragma unroll
            for (int j = 0; j < 8; j++) {
                int c = tcol + 16 * j;
                out[row * ND + c] = nf[row * ND + c] + acc2[i][j];
            }
        }
    }
}

extern "C" void kernel_launch(void* const* d_in, const int* in_sizes, int n_in,
                              void* d_out, int out_size)
{
    const float* nf   = (const float*)d_in[0];
    const float* ef   = (const float*)d_in[1];
    const int*   eidx = (const int*)  d_in[2];
    const float* w1   = (const float*)d_in[3];
    const float* b1   = (const float*)d_in[4];
    const float* g1   = (const float*)d_in[5];
    const float* be1  = (const float*)d_in[6];
    const float* w2   = (const float*)d_in[7];
    const float* b2   = (const float*)d_in[8];
    const float* uw1  = (const float*)d_in[9];
    const float* ub1  = (const float*)d_in[10];
    const float* g2   = (const float*)d_in[11];
    const float* be2  = (const float*)d_in[12];
    const float* uw2  = (const float*)d_in[13];
    const float* ub2  = (const float*)d_in[14];
    float* out = (float*)d_out;

    zero_agg_kernel<<<592, 256>>>();
    msg_kernel<<<(2 * E_EDGES) / 64, 256>>>(nf, ef, eidx, w1, b1, g1, be1, w2, b2);
    upd_kernel<<<(N_NODES + 63) / 64, 256>>>(nf, uw1, ub1, g2, be2, uw2, ub2, out);
}

// round 2
// speedup vs baseline: 1.4282x; 1.4282x over previous
#include <cuda_runtime.h>
#include <math.h>

#define N_NODES 100000
#define E_EDGES 400000
#define ND 128
#define ED 64
#define HD 128
#define LN_EPS 1e-5f

typedef unsigned long long ull;

// Scratch (allocation-free rule: __device__ globals)
__device__ float g_agg[(size_t)N_NODES * HD];
__device__ float g_P[(size_t)N_NODES * HD];    // nf @ W1[0:128]
__device__ float g_Q[(size_t)N_NODES * HD];    // nf @ W1[128:256]
__device__ float g_R[(size_t)E_EDGES * HD];    // ef @ W1[256:320] + b1

// ---------------- helpers: packed f32x2 FMA ----------------
__device__ __forceinline__ void ffma2(ull& d, ull a, ull b) {
    asm("fma.rn.f32x2 %0, %1, %2, %0;" : "+l"(d) : "l"(a), "l"(b));
}
__device__ __forceinline__ ull pack2(float x, float y) {
    ull r; asm("mov.b64 %0, {%1, %2};" : "=l"(r) : "f"(x), "f"(y)); return r;
}
__device__ __forceinline__ ull pack2dup(float x) {
    ull r; asm("mov.b64 %0, {%1, %1};" : "=l"(r) : "f"(x)); return r;
}
__device__ __forceinline__ float2 unpack2(ull v) {
    float2 r; asm("mov.b64 {%0, %1}, %2;" : "=f"(r.x), "=f"(r.y) : "l"(v)); return r;
}
__device__ __forceinline__ void red_add_v4(float* p, float a, float b, float c, float d) {
    asm volatile("red.global.add.v4.f32 [%0], {%1, %2, %3, %4};"
                 :: "l"(p), "f"(a), "f"(b), "f"(c), "f"(d) : "memory");
}

__global__ void zero_agg_kernel() {
    float4* p = reinterpret_cast<float4*>(g_agg);
    const int n4 = N_NODES * HD / 4;
    for (int i = blockIdx.x * blockDim.x + threadIdx.x; i < n4;
         i += gridDim.x * blockDim.x)
        p[i] = make_float4(0.f, 0.f, 0.f, 0.f);
}

// ---------------------------------------------------------------------------
// Generic tiled GEMM: C[M][128] = A[M][K] @ W[K][128] (+bias), K multiple of 16.
// 256 threads, 64 rows/block. Thread tile: rows r0..r0+3, cols tcol*4+64*j4+q.
// FFMA2 inner loop.
// ---------------------------------------------------------------------------
__global__ __launch_bounds__(256) void gemm128_kernel(
    const float* __restrict__ A, int M, int K,
    const float* __restrict__ W, const float* __restrict__ bias,
    float* __restrict__ C)
{
    __shared__ float Xs[64][20];
    __shared__ float Ws[16][128];

    const int tid = threadIdx.x;
    const long rBase = (long)blockIdx.x * 64;
    const int trow = tid >> 4, tcol = tid & 15;
    const int r0 = trow * 4;
    const int lr = tid >> 2, lc4 = tid & 3;
    long rowL = rBase + lr;
    if (rowL >= M) rowL = M - 1;

    ull acc[4][4];
    {
        float4 b0 = bias ? *(const float4*)&bias[tcol * 4]
                         : make_float4(0.f, 0.f, 0.f, 0.f);
        float4 b1v = bias ? *(const float4*)&bias[tcol * 4 + 64]
                          : make_float4(0.f, 0.f, 0.f, 0.f);
        ull p0 = pack2(b0.x, b0.y), p1 = pack2(b0.z, b0.w);
        ull p2 = pack2(b1v.x, b1v.y), p3 = pack2(b1v.z, b1v.w);
        #pragma unroll
        for (int i = 0; i < 4; i++) {
            acc[i][0] = p0; acc[i][1] = p1; acc[i][2] = p2; acc[i][3] = p3;
        }
    }

    for (int kc = 0; kc < K; kc += 16) {
        float4 xv = *(const float4*)(A + rowL * K + kc + lc4 * 4);
        float4 wv0 = *(const float4*)(W + (long)(kc + (tid >> 5)) * 128 + (tid & 31) * 4);
        float4 wv1 = *(const float4*)(W + (long)(kc + 8 + (tid >> 5)) * 128 + (tid & 31) * 4);
        __syncthreads();
        *(float4*)&Xs[lr][lc4 * 4] = xv;
        *(float4*)&Ws[tid >> 5][(tid & 31) * 4] = wv0;
        *(float4*)&Ws[8 + (tid >> 5)][(tid & 31) * 4] = wv1;
        __syncthreads();
        #pragma unroll
        for (int k = 0; k < 16; k++) {
            ull xa[4];
            #pragma unroll
            for (int i = 0; i < 4; i++) xa[i] = pack2dup(Xs[r0 + i][k]);
            ulonglong2 w0 = *(const ulonglong2*)&Ws[k][tcol * 4];
            ulonglong2 w1 = *(const ulonglong2*)&Ws[k][tcol * 4 + 64];
            #pragma unroll
            for (int i = 0; i < 4; i++) {
                ffma2(acc[i][0], xa[i], w0.x);
                ffma2(acc[i][1], xa[i], w0.y);
                ffma2(acc[i][2], xa[i], w1.x);
                ffma2(acc[i][3], xa[i], w1.y);
            }
        }
    }

    #pragma unroll
    for (int i = 0; i < 4; i++) {
        long row = rBase + r0 + i;
        if (row < M) {
            float2 a0 = unpack2(acc[i][0]), a1 = unpack2(acc[i][1]);
            float2 a2 = unpack2(acc[i][2]), a3 = unpack2(acc[i][3]);
            *(float4*)(C + row * 128 + tcol * 4)      = make_float4(a0.x, a0.y, a1.x, a1.y);
            *(float4*)(C + row * 128 + tcol * 4 + 64) = make_float4(a2.x, a2.y, a3.x, a3.y);
        }
    }
}

// ---------------------------------------------------------------------------
// Message kernel v2: 64 edges/block.
// Phase A: h1 = P[src] + Q[tgt] + R[e]  (R carries b1); LN + ReLU -> Hs.
// Phase B: M = Hs @ w2 + b2 (FFMA2); red.v4 scatter into g_agg[tgt].
// ---------------------------------------------------------------------------
__global__ __launch_bounds__(256) void msg2_kernel(
    const int* __restrict__ eidx,
    const float* __restrict__ g1, const float* __restrict__ be1,
    const float* __restrict__ w2, const float* __restrict__ b2)
{
    __shared__ float Hs[64][132];
    __shared__ float Ws[16][128];
    __shared__ int sSrc[64], sTgt[64];

    const int tid = threadIdx.x;
    const long eBase = (long)blockIdx.x * 64;
    const int wid = tid >> 5, lane = tid & 31;

    if (tid < 64) {
        long e = eBase + tid;
        int s, t;
        if (e < E_EDGES) { s = eidx[e]; t = eidx[E_EDGES + e]; }
        else { long e2 = e - E_EDGES; s = eidx[E_EDGES + e2]; t = eidx[e2]; }
        sSrc[tid] = s; sTgt[tid] = t;
    }
    __syncthreads();

    // ---- Phase A: gather-sum + LayerNorm + ReLU (one warp per row) ----
    for (int it = 0; it < 8; it++) {
        int row = it * 8 + wid;
        int s = sSrc[row], t = sTgt[row];
        long e = eBase + row;
        long er = (e < E_EDGES) ? e : e - E_EDGES;
        float4 a = *(const float4*)(g_P + (long)s * 128 + lane * 4);
        float4 b = *(const float4*)(g_Q + (long)t * 128 + lane * 4);
        float4 c = *(const float4*)(g_R + er * 128 + lane * 4);
        float4 v = make_float4(a.x + b.x + c.x, a.y + b.y + c.y,
                               a.z + b.z + c.z, a.w + b.w + c.w);
        float s1 = v.x + v.y + v.z + v.w;
        float ss = v.x * v.x + v.y * v.y + v.z * v.z + v.w * v.w;
        #pragma unroll
        for (int o = 16; o >= 1; o >>= 1) {
            s1 += __shfl_xor_sync(0xffffffffu, s1, o);
            ss += __shfl_xor_sync(0xffffffffu, ss, o);
        }
        float mean = s1 * (1.0f / HD);
        float var  = ss * (1.0f / HD) - mean * mean;
        float rstd = rsqrtf(var + LN_EPS);
        float4 gg = *(const float4*)&g1[lane * 4];
        float4 bb = *(const float4*)&be1[lane * 4];
        v.x = fmaxf((v.x - mean) * rstd * gg.x + bb.x, 0.f);
        v.y = fmaxf((v.y - mean) * rstd * gg.y + bb.y, 0.f);
        v.z = fmaxf((v.z - mean) * rstd * gg.z + bb.z, 0.f);
        v.w = fmaxf((v.w - mean) * rstd * gg.w + bb.w, 0.f);
        *(float4*)&Hs[row][lane * 4] = v;
    }

    // ---- Phase B: GEMM2 ----
    const int trow = tid >> 4, tcol = tid & 15;
    const int r0 = trow * 4;
    ull acc[4][4];
    {
        float4 b0 = *(const float4*)&b2[tcol * 4];
        float4 b1v = *(const float4*)&b2[tcol * 4 + 64];
        ull p0 = pack2(b0.x, b0.y), p1 = pack2(b0.z, b0.w);
        ull p2 = pack2(b1v.x, b1v.y), p3 = pack2(b1v.z, b1v.w);
        #pragma unroll
        for (int i = 0; i < 4; i++) {
            acc[i][0] = p0; acc[i][1] = p1; acc[i][2] = p2; acc[i][3] = p3;
        }
    }

    for (int kc = 0; kc < HD; kc += 16) {
        float4 wv0 = *(const float4*)(w2 + (long)(kc + (tid >> 5)) * 128 + (tid & 31) * 4);
        float4 wv1 = *(const float4*)(w2 + (long)(kc + 8 + (tid >> 5)) * 128 + (tid & 31) * 4);
        __syncthreads();
        *(float4*)&Ws[tid >> 5][(tid & 31) * 4] = wv0;
        *(float4*)&Ws[8 + (tid >> 5)][(tid & 31) * 4] = wv1;
        __syncthreads();
        #pragma unroll
        for (int k = 0; k < 16; k++) {
            ull xa[4];
            #pragma unroll
            for (int i = 0; i < 4; i++) xa[i] = pack2dup(Hs[r0 + i][kc + k]);
            ulonglong2 w0 = *(const ulonglong2*)&Ws[k][tcol * 4];
            ulonglong2 w1 = *(const ulonglong2*)&Ws[k][tcol * 4 + 64];
            #pragma unroll
            for (int i = 0; i < 4; i++) {
                ffma2(acc[i][0], xa[i], w0.x);
                ffma2(acc[i][1], xa[i], w0.y);
                ffma2(acc[i][2], xa[i], w1.x);
                ffma2(acc[i][3], xa[i], w1.y);
            }
        }
    }

    // ---- scatter-add (vectorized reductions) ----
    #pragma unroll
    for (int i = 0; i < 4; i++) {
        float* dst = g_agg + (long)sTgt[r0 + i] * 128;
        float2 a0 = unpack2(acc[i][0]), a1 = unpack2(acc[i][1]);
        float2 a2 = unpack2(acc[i][2]), a3 = unpack2(acc[i][3]);
        red_add_v4(dst + tcol * 4,      a0.x, a0.y, a1.x, a1.y);
        red_add_v4(dst + tcol * 4 + 64, a2.x, a2.y, a3.x, a3.y);
    }
}

// ---------------------------------------------------------------------------
// Update kernel: 64 nodes/block.
//   U = [nf | agg]; out = nf + (relu(LN(U@uw1+ub1)) @ uw2 + ub2)   (FFMA2)
// ---------------------------------------------------------------------------
__global__ __launch_bounds__(256) void upd_kernel(
    const float* __restrict__ nf,
    const float* __restrict__ uw1, const float* __restrict__ ub1,
    const float* __restrict__ g2, const float* __restrict__ be2,
    const float* __restrict__ uw2, const float* __restrict__ ub2,
    float* __restrict__ out)
{
    __shared__ float Xs[64][20];
    __shared__ float Ws[16][128];
    __shared__ float Hs[64][132];

    const int tid = threadIdx.x;
    const long nBase = (long)blockIdx.x * 64;
    const int trow = tid >> 4, tcol = tid & 15;
    const int r0 = trow * 4;
    const int lr = tid >> 2, lc4 = tid & 3;
    long rowL = nBase + lr;
    if (rowL >= N_NODES) rowL = N_NODES - 1;

    ull acc[4][4];
    {
        float4 b0 = *(const float4*)&ub1[tcol * 4];
        float4 b1v = *(const float4*)&ub1[tcol * 4 + 64];
        ull p0 = pack2(b0.x, b0.y), p1 = pack2(b0.z, b0.w);
        ull p2 = pack2(b1v.x, b1v.y), p3 = pack2(b1v.z, b1v.w);
        #pragma unroll
        for (int i = 0; i < 4; i++) {
            acc[i][0] = p0; acc[i][1] = p1; acc[i][2] = p2; acc[i][3] = p3;
        }
    }

    // ---- GEMM1: K = 256 ----
    for (int kc = 0; kc < ND + HD; kc += 16) {
        const float* srcp = (kc < ND) ? (nf + rowL * ND + kc)
                                      : (g_agg + rowL * HD + (kc - ND));
        float4 xv = *(const float4*)(srcp + lc4 * 4);
        float4 wv0 = *(const float4*)(uw1 + (long)(kc + (tid >> 5)) * 128 + (tid & 31) * 4);
        float4 wv1 = *(const float4*)(uw1 + (long)(kc + 8 + (tid >> 5)) * 128 + (tid & 31) * 4);
        __syncthreads();
        *(float4*)&Xs[lr][lc4 * 4] = xv;
        *(float4*)&Ws[tid >> 5][(tid & 31) * 4] = wv0;
        *(float4*)&Ws[8 + (tid >> 5)][(tid & 31) * 4] = wv1;
        __syncthreads();
        #pragma unroll
        for (int k = 0; k < 16; k++) {
            ull xa[4];
            #pragma unroll
            for (int i = 0; i < 4; i++) xa[i] = pack2dup(Xs[r0 + i][k]);
            ulonglong2 w0 = *(const ulonglong2*)&Ws[k][tcol * 4];
            ulonglong2 w1 = *(const ulonglong2*)&Ws[k][tcol * 4 + 64];
            #pragma unroll
            for (int i = 0; i < 4; i++) {
                ffma2(acc[i][0], xa[i], w0.x);
                ffma2(acc[i][1], xa[i], w0.y);
                ffma2(acc[i][2], xa[i], w1.x);
                ffma2(acc[i][3], xa[i], w1.y);
            }
        }
    }

    // ---- LN + ReLU -> Hs ----
    #pragma unroll
    for (int i = 0; i < 4; i++) {
        float2 a0 = unpack2(acc[i][0]), a1 = unpack2(acc[i][1]);
        float2 a2 = unpack2(acc[i][2]), a3 = unpack2(acc[i][3]);
        float va[8] = {a0.x, a0.y, a1.x, a1.y, a2.x, a2.y, a3.x, a3.y};
        float s = 0.f, ss = 0.f;
        #pragma unroll
        for (int j = 0; j < 8; j++) { s += va[j]; ss += va[j] * va[j]; }
        #pragma unroll
        for (int o = 8; o >= 1; o >>= 1) {
            s  += __shfl_xor_sync(0xffffffffu, s,  o);
            ss += __shfl_xor_sync(0xffffffffu, ss, o);
        }
        float mean = s * (1.0f / HD);
        float var  = ss * (1.0f / HD) - mean * mean;
        float rstd = rsqrtf(var + LN_EPS);
        float4 h0, h1;
        {
            int c = tcol * 4;
            float4 gg = *(const float4*)&g2[c];
            float4 bb = *(const float4*)&be2[c];
            h0.x = fmaxf((va[0] - mean) * rstd * gg.x + bb.x, 0.f);
            h0.y = fmaxf((va[1] - mean) * rstd * gg.y + bb.y, 0.f);
            h0.z = fmaxf((va[2] - mean) * rstd * gg.z + bb.z, 0.f);
            h0.w = fmaxf((va[3] - mean) * rstd * gg.w + bb.w, 0.f);
            gg = *(const float4*)&g2[c + 64];
            bb = *(const float4*)&be2[c + 64];
            h1.x = fmaxf((va[4] - mean) * rstd * gg.x + bb.x, 0.f);
            h1.y = fmaxf((va[5] - mean) * rstd * gg.y + bb.y, 0.f);
            h1.z = fmaxf((va[6] - mean) * rstd * gg.z + bb.z, 0.f);
            h1.w = fmaxf((va[7] - mean) * rstd * gg.w + bb.w, 0.f);
        }
        *(float4*)&Hs[r0 + i][tcol * 4]      = h0;
        *(float4*)&Hs[r0 + i][tcol * 4 + 64] = h1;
    }

    // ---- GEMM2: K = 128 ----
    ull acc2[4][4];
    {
        float4 b0 = *(const float4*)&ub2[tcol * 4];
        float4 b1v = *(const float4*)&ub2[tcol * 4 + 64];
        ull p0 = pack2(b0.x, b0.y), p1 = pack2(b0.z, b0.w);
        ull p2 = pack2(b1v.x, b1v.y), p3 = pack2(b1v.z, b1v.w);
        #pragma unroll
        for (int i = 0; i < 4; i++) {
            acc2[i][0] = p0; acc2[i][1] = p1; acc2[i][2] = p2; acc2[i][3] = p3;
        }
    }
    for (int kc = 0; kc < HD; kc += 16) {
        float4 wv0 = *(const float4*)(uw2 + (long)(kc + (tid >> 5)) * 128 + (tid & 31) * 4);
        float4 wv1 = *(const float4*)(uw2 + (long)(kc + 8 + (tid >> 5)) * 128 + (tid & 31) * 4);
        __syncthreads();
        *(float4*)&Ws[tid >> 5][(tid & 31) * 4] = wv0;
        *(float4*)&Ws[8 + (tid >> 5)][(tid & 31) * 4] = wv1;
        __syncthreads();
        #pragma unroll
        for (int k = 0; k < 16; k++) {
            ull xa[4];
            #pragma unroll
            for (int i = 0; i < 4; i++) xa[i] = pack2dup(Hs[r0 + i][kc + k]);
            ulonglong2 w0 = *(const ulonglong2*)&Ws[k][tcol * 4];
            ulonglong2 w1 = *(const ulonglong2*)&Ws[k][tcol * 4 + 64];
            #pragma unroll
            for (int i = 0; i < 4; i++) {
                ffma2(acc2[i][0], xa[i], w0.x);
                ffma2(acc2[i][1], xa[i], w0.y);
                ffma2(acc2[i][2], xa[i], w1.x);
                ffma2(acc2[i][3], xa[i], w1.y);
            }
        }
    }

    // ---- residual + store ----
    #pragma unroll
    for (int i = 0; i < 4; i++) {
        long row = nBase + r0 + i;
        if (row < N_NODES) {
            float2 a0 = unpack2(acc2[i][0]), a1 = unpack2(acc2[i][1]);
            float2 a2 = unpack2(acc2[i][2]), a3 = unpack2(acc2[i][3]);
            int c = tcol * 4;
            float4 n0 = *(const float4*)(nf + row * ND + c);
            float4 n1 = *(const float4*)(nf + row * ND + c + 64);
            *(float4*)(out + row * ND + c) =
                make_float4(n0.x + a0.x, n0.y + a0.y, n0.z + a1.x, n0.w + a1.y);
            *(float4*)(out + row * ND + c + 64) =
                make_float4(n1.x + a2.x, n1.y + a2.y, n1.z + a3.x, n1.w + a3.y);
        }
    }
}

extern "C" void kernel_launch(void* const* d_in, const int* in_sizes, int n_in,
                              void* d_out, int out_size)
{
    const float* nf   = (const float*)d_in[0];
    const float* ef   = (const float*)d_in[1];
    const int*   eidx = (const int*)  d_in[2];
    const float* w1   = (const float*)d_in[3];
    const float* b1   = (const float*)d_in[4];
    const float* g1   = (const float*)d_in[5];
    const float* be1  = (const float*)d_in[6];
    const float* w2   = (const float*)d_in[7];
    const float* b2   = (const float*)d_in[8];
    const float* uw1  = (const float*)d_in[9];
    const float* ub1  = (const float*)d_in[10];
    const float* g2   = (const float*)d_in[11];
    const float* be2  = (const float*)d_in[12];
    const float* uw2  = (const float*)d_in[13];
    const float* ub2  = (const float*)d_in[14];
    float* out = (float*)d_out;

    float* dP; float* dQ; float* dR;
    cudaGetSymbolAddress((void**)&dP, g_P);
    cudaGetSymbolAddress((void**)&dQ, g_Q);
    cudaGetSymbolAddress((void**)&dR, g_R);

    zero_agg_kernel<<<592, 256>>>();
    // P = nf @ W1[0:128], Q = nf @ W1[128:256], R = ef @ W1[256:320] + b1
    gemm128_kernel<<<(N_NODES + 63) / 64, 256>>>(nf, N_NODES, ND, w1, nullptr, dP);
    gemm128_kernel<<<(N_NODES + 63) / 64, 256>>>(nf, N_NODES, ND, w1 + ND * HD, nullptr, dQ);
    gemm128_kernel<<<(E_EDGES + 63) / 64, 256>>>(ef, E_EDGES, ED, w1 + 2 * ND * HD, b1, dR);
    msg2_kernel<<<(2 * E_EDGES) / 64, 256>>>(eidx, g1, be1, w2, b2);
    upd_kernel<<<(N_NODES + 63) / 64, 256>>>(nf, uw1, ub1, g2, be2, uw2, ub2, out);
}

// round 3
// speedup vs baseline: 2.8953x; 2.0273x over previous
#include <cuda_runtime.h>
#include <math.h>

#define N_NODES 100000
#define E_EDGES 400000
#define ND 128
#define ED 64
#define HD 128
#define LN_EPS 1e-5f

typedef unsigned long long ull;

// Scratch (__device__ globals: allocation-free rule)
__device__ float g_hagg[(size_t)N_NODES * HD];  // sum of h over incoming edges
__device__ float g_deg[N_NODES];                // in-degree (float)
__device__ float g_P[(size_t)N_NODES * HD];     // nf @ W1a
__device__ float g_Q[(size_t)N_NODES * HD];     // nf @ W1b
__device__ float g_R[(size_t)E_EDGES * HD];     // ef @ W1c + b1
__device__ float g_H[(size_t)N_NODES * HD];     // relu(LN(update pre-act))
__device__ float g_W2p[HD * HD];                // W2 @ uw1b
__device__ float g_d2[HD];                      // b2 @ uw1b

// ---------------- packed f32x2 helpers ----------------
__device__ __forceinline__ void ffma2(ull& d, ull a, ull b) {
    asm("fma.rn.f32x2 %0, %1, %2, %0;" : "+l"(d) : "l"(a), "l"(b));
}
__device__ __forceinline__ ull pack2(float x, float y) {
    ull r; asm("mov.b64 %0, {%1, %2};" : "=l"(r) : "f"(x), "f"(y)); return r;
}
__device__ __forceinline__ ull pack2dup(float x) {
    ull r; asm("mov.b64 %0, {%1, %1};" : "=l"(r) : "f"(x)); return r;
}
__device__ __forceinline__ float2 unpack2(ull v) {
    float2 r; asm("mov.b64 {%0, %1}, %2;" : "=f"(r.x), "=f"(r.y) : "l"(v)); return r;
}
__device__ __forceinline__ void red_add_v4(float* p, float a, float b, float c, float d) {
    asm volatile("red.global.add.v4.f32 [%0], {%1, %2, %3, %4};"
                 :: "l"(p), "f"(a), "f"(b), "f"(c), "f"(d) : "memory");
}
__device__ __forceinline__ void red_add_f32(float* p, float v) {
    asm volatile("red.global.add.f32 [%0], %1;" :: "l"(p), "f"(v) : "memory");
}

__global__ void zero_kernel() {
    float4* p = reinterpret_cast<float4*>(g_hagg);
    const int n4 = N_NODES * HD / 4;
    for (int i = blockIdx.x * blockDim.x + threadIdx.x; i < n4;
         i += gridDim.x * blockDim.x)
        p[i] = make_float4(0.f, 0.f, 0.f, 0.f);
    for (int i = blockIdx.x * blockDim.x + threadIdx.x; i < N_NODES;
         i += gridDim.x * blockDim.x)
        g_deg[i] = 0.f;
}

// d2 = b2 @ uw1b   (uw1 rows 128..255)
__global__ void d2_kernel(const float* __restrict__ uw1, const float* __restrict__ b2) {
    int j = threadIdx.x;
    float s = 0.f;
    for (int k = 0; k < HD; k++)
        s = fmaf(b2[k], uw1[(ND + k) * HD + j], s);
    g_d2[j] = s;
}

// ---------------------------------------------------------------------------
// gemm128b: C[M][128] = A[M][K] @ W[K][128] (+bias) (+resid), K % 16 == 0.
// 256 threads, 128 rows/block, 8x8 per-thread tile, FFMA2.
// ---------------------------------------------------------------------------
__global__ __launch_bounds__(256) void gemm128b(
    const float* __restrict__ A, int M, int K,
    const float* __restrict__ W, const float* __restrict__ bias,
    const float* __restrict__ resid, float* __restrict__ C)
{
    __shared__ float Xs[128][20];
    __shared__ float Ws[16][128];

    const int tid = threadIdx.x;
    const long rBase = (long)blockIdx.x * 128;
    const int trow = tid >> 4, tcol = tid & 15;
    const int r0 = trow * 8;
    // loaders: 2 float4 each for Xs (rows tid>>2 and +64), 2 for Ws
    const int lrA = tid >> 2, lqA = tid & 3;
    const int lkW = tid >> 5, lcW = tid & 31;
    long rowA0 = rBase + lrA;        if (rowA0 >= M) rowA0 = M - 1;
    long rowA1 = rBase + lrA + 64;   if (rowA1 >= M) rowA1 = M - 1;

    ull acc[8][4];
    {
        ull p0, p1, p2, p3;
        if (bias) {
            float4 b0 = *(const float4*)&bias[tcol * 4];
            float4 b1 = *(const float4*)&bias[tcol * 4 + 64];
            p0 = pack2(b0.x, b0.y); p1 = pack2(b0.z, b0.w);
            p2 = pack2(b1.x, b1.y); p3 = pack2(b1.z, b1.w);
        } else { p0 = p1 = p2 = p3 = 0ull; }
        #pragma unroll
        for (int i = 0; i < 8; i++) {
            acc[i][0] = p0; acc[i][1] = p1; acc[i][2] = p2; acc[i][3] = p3;
        }
    }

    for (int kc = 0; kc < K; kc += 16) {
        float4 x0 = *(const float4*)(A + rowA0 * K + kc + lqA * 4);
        float4 x1 = *(const float4*)(A + rowA1 * K + kc + lqA * 4);
        float4 w0 = *(const float4*)(W + (long)(kc + lkW) * 128 + lcW * 4);
        float4 w1 = *(const float4*)(W + (long)(kc + 8 + lkW) * 128 + lcW * 4);
        __syncthreads();
        *(float4*)&Xs[lrA][lqA * 4]      = x0;
        *(float4*)&Xs[lrA + 64][lqA * 4] = x1;
        *(float4*)&Ws[lkW][lcW * 4]      = w0;
        *(float4*)&Ws[lkW + 8][lcW * 4]  = w1;
        __syncthreads();
        #pragma unroll
        for (int k = 0; k < 16; k++) {
            ulonglong2 wv0 = *(const ulonglong2*)&Ws[k][tcol * 4];
            ulonglong2 wv1 = *(const ulonglong2*)&Ws[k][tcol * 4 + 64];
            #pragma unroll
            for (int i = 0; i < 8; i++) {
                ull xa = pack2dup(Xs[r0 + i][k]);
                ffma2(acc[i][0], xa, wv0.x);
                ffma2(acc[i][1], xa, wv0.y);
                ffma2(acc[i][2], xa, wv1.x);
                ffma2(acc[i][3], xa, wv1.y);
            }
        }
    }

    #pragma unroll
    for (int i = 0; i < 8; i++) {
        long row = rBase + r0 + i;
        if (row < M) {
            float2 a0 = unpack2(acc[i][0]), a1 = unpack2(acc[i][1]);
            float2 a2 = unpack2(acc[i][2]), a3 = unpack2(acc[i][3]);
            float4 v0 = make_float4(a0.x, a0.y, a1.x, a1.y);
            float4 v1 = make_float4(a2.x, a2.y, a3.x, a3.y);
            int c = tcol * 4;
            if (resid) {
                float4 n0 = *(const float4*)(resid + row * 128 + c);
                float4 n1 = *(const float4*)(resid + row * 128 + c + 64);
                v0.x += n0.x; v0.y += n0.y; v0.z += n0.z; v0.w += n0.w;
                v1.x += n1.x; v1.y += n1.y; v1.z += n1.z; v1.w += n1.w;
            }
            *(float4*)(C + row * 128 + c)      = v0;
            *(float4*)(C + row * 128 + c + 64) = v1;
        }
    }
}

// ---------------------------------------------------------------------------
// Edge kernel: one warp per bidirectional edge.
//   h = relu(LN(P[src] + Q[tgt] + R[er]))   (R carries b1)
//   red.v4 into g_hagg[tgt]; deg count.
// ---------------------------------------------------------------------------
__global__ __launch_bounds__(256) void edge_kernel(
    const int* __restrict__ eidx,
    const float* __restrict__ g1, const float* __restrict__ be1)
{
    const int wid = threadIdx.x >> 5, lane = threadIdx.x & 31;
    const long e = (long)blockIdx.x * 8 + wid;
    int s, t; long er;
    if (e < E_EDGES) { er = e; s = eidx[e]; t = eidx[E_EDGES + e]; }
    else             { er = e - E_EDGES; s = eidx[E_EDGES + er]; t = eidx[er]; }

    float4 a = *(const float4*)(g_P + (long)s * HD + lane * 4);
    float4 b = *(const float4*)(g_Q + (long)t * HD + lane * 4);
    float4 c = *(const float4*)(g_R + er * HD + lane * 4);
    float4 v = make_float4(a.x + b.x + c.x, a.y + b.y + c.y,
                           a.z + b.z + c.z, a.w + b.w + c.w);
    float s1 = v.x + v.y + v.z + v.w;
    float ss = v.x * v.x + v.y * v.y + v.z * v.z + v.w * v.w;
    #pragma unroll
    for (int o = 16; o >= 1; o >>= 1) {
        s1 += __shfl_xor_sync(0xffffffffu, s1, o);
        ss += __shfl_xor_sync(0xffffffffu, ss, o);
    }
    float mean = s1 * (1.0f / HD);
    float var  = ss * (1.0f / HD) - mean * mean;
    float rstd = rsqrtf(var + LN_EPS);
    float4 gg = *(const float4*)&g1[lane * 4];
    float4 bb = *(const float4*)&be1[lane * 4];
    float h0 = fmaxf((v.x - mean) * rstd * gg.x + bb.x, 0.f);
    float h1 = fmaxf((v.y - mean) * rstd * gg.y + bb.y, 0.f);
    float h2 = fmaxf((v.z - mean) * rstd * gg.z + bb.z, 0.f);
    float h3 = fmaxf((v.w - mean) * rstd * gg.w + bb.w, 0.f);
    red_add_v4(g_hagg + (long)t * HD + lane * 4, h0, h1, h2, h3);
    if (lane == 0) red_add_f32(g_deg + t, 1.0f);
}

// ---------------------------------------------------------------------------
// upd1: T = nf@uw1a + hagg@W2p + deg*d2 + ub1; g_H = relu(LN(T))
// Same 8x8 microkernel; LN epilogue across half-warp (16 lanes own a row).
// ---------------------------------------------------------------------------
__global__ __launch_bounds__(256) void upd1_kernel(
    const float* __restrict__ nf, const float* __restrict__ uw1,
    const float* __restrict__ ub1,
    const float* __restrict__ g2, const float* __restrict__ be2)
{
    __shared__ float Xs[128][20];
    __shared__ float Ws[16][128];

    const int tid = threadIdx.x;
    const long rBase = (long)blockIdx.x * 128;
    const int trow = tid >> 4, tcol = tid & 15;
    const int r0 = trow * 8;
    const int lrA = tid >> 2, lqA = tid & 3;
    const int lkW = tid >> 5, lcW = tid & 31;
    long rowA0 = rBase + lrA;        if (rowA0 >= N_NODES) rowA0 = N_NODES - 1;
    long rowA1 = rBase + lrA + 64;   if (rowA1 >= N_NODES) rowA1 = N_NODES - 1;

    ull acc[8][4];
    {
        float4 b0 = *(const float4*)&ub1[tcol * 4];
        float4 b1 = *(const float4*)&ub1[tcol * 4 + 64];
        ull p0 = pack2(b0.x, b0.y), p1 = pack2(b0.z, b0.w);
        ull p2 = pack2(b1.x, b1.y), p3 = pack2(b1.z, b1.w);
        #pragma unroll
        for (int i = 0; i < 8; i++) {
            acc[i][0] = p0; acc[i][1] = p1; acc[i][2] = p2; acc[i][3] = p3;
        }
    }

    #pragma unroll 1
    for (int seg = 0; seg < 2; seg++) {
        const float* A = seg ? g_hagg : nf;
        const float* W = seg ? g_W2p : uw1;      // uw1 rows 0..127 = uw1a
        for (int kc = 0; kc < HD; kc += 16) {
            float4 x0 = *(const float4*)(A + rowA0 * HD + kc + lqA * 4);
            float4 x1 = *(const float4*)(A + rowA1 * HD + kc + lqA * 4);
            float4 w0 = *(const float4*)(W + (long)(kc + lkW) * 128 + lcW * 4);
            float4 w1 = *(const float4*)(W + (long)(kc + 8 + lkW) * 128 + lcW * 4);
            __syncthreads();
            *(float4*)&Xs[lrA][lqA * 4]      = x0;
            *(float4*)&Xs[lrA + 64][lqA * 4] = x1;
            *(float4*)&Ws[lkW][lcW * 4]      = w0;
            *(float4*)&Ws[lkW + 8][lcW * 4]  = w1;
            __syncthreads();
            #pragma unroll
            for (int k = 0; k < 16; k++) {
                ulonglong2 wv0 = *(const ulonglong2*)&Ws[k][tcol * 4];
                ulonglong2 wv1 = *(const ulonglong2*)&Ws[k][tcol * 4 + 64];
                #pragma unroll
                for (int i = 0; i < 8; i++) {
                    ull xa = pack2dup(Xs[r0 + i][k]);
                    ffma2(acc[i][0], xa, wv0.x);
                    ffma2(acc[i][1], xa, wv0.y);
                    ffma2(acc[i][2], xa, wv1.x);
                    ffma2(acc[i][3], xa, wv1.y);
                }
            }
        }
    }

    // epilogue: + deg*d2, LayerNorm (16 lanes per row), ReLU, store g_H
    float4 d20 = *(const float4*)&g_d2[tcol * 4];
    float4 d21 = *(const float4*)&g_d2[tcol * 4 + 64];
    float4 gg0 = *(const float4*)&g2[tcol * 4];
    float4 gg1 = *(const float4*)&g2[tcol * 4 + 64];
    float4 bb0 = *(const float4*)&be2[tcol * 4];
    float4 bb1 = *(const float4*)&be2[tcol * 4 + 64];

    #pragma unroll
    for (int i = 0; i < 8; i++) {
        long row = rBase + r0 + i;
        long rowc = row < N_NODES ? row : N_NODES - 1;
        float dg = g_deg[rowc];
        float2 a0 = unpack2(acc[i][0]), a1 = unpack2(acc[i][1]);
        float2 a2 = unpack2(acc[i][2]), a3 = unpack2(acc[i][3]);
        float va[8];
        va[0] = a0.x + dg * d20.x; va[1] = a0.y + dg * d20.y;
        va[2] = a1.x + dg * d20.z; va[3] = a1.y + dg * d20.w;
        va[4] = a2.x + dg * d21.x; va[5] = a2.y + dg * d21.y;
        va[6] = a3.x + dg * d21.z; va[7] = a3.y + dg * d21.w;
        float s = 0.f, ss = 0.f;
        #pragma unroll
        for (int j = 0; j < 8; j++) { s += va[j]; ss += va[j] * va[j]; }
        #pragma unroll
        for (int o = 8; o >= 1; o >>= 1) {
            s  += __shfl_xor_sync(0xffffffffu, s,  o);
            ss += __shfl_xor_sync(0xffffffffu, ss, o);
        }
        float mean = s * (1.0f / HD);
        float var  = ss * (1.0f / HD) - mean * mean;
        float rstd = rsqrtf(var + LN_EPS);
        if (row < N_NODES) {
            float4 h0, h1;
            h0.x = fmaxf((va[0] - mean) * rstd * gg0.x + bb0.x, 0.f);
            h0.y = fmaxf((va[1] - mean) * rstd * gg0.y + bb0.y, 0.f);
            h0.z = fmaxf((va[2] - mean) * rstd * gg0.z + bb0.z, 0.f);
            h0.w = fmaxf((va[3] - mean) * rstd * gg0.w + bb0.w, 0.f);
            h1.x = fmaxf((va[4] - mean) * rstd * gg1.x + bb1.x, 0.f);
            h1.y = fmaxf((va[5] - mean) * rstd * gg1.y + bb1.y, 0.f);
            h1.z = fmaxf((va[6] - mean) * rstd * gg1.z + bb1.z, 0.f);
            h1.w = fmaxf((va[7] - mean) * rstd * gg1.w + bb1.w, 0.f);
            *(float4*)(g_H + row * HD + tcol * 4)      = h0;
            *(float4*)(g_H + row * HD + tcol * 4 + 64) = h1;
        }
    }
}

extern "C" void kernel_launch(void* const* d_in, const int* in_sizes, int n_in,
                              void* d_out, int out_size)
{
    const float* nf   = (const float*)d_in[0];
    const float* ef   = (const float*)d_in[1];
    const int*   eidx = (const int*)  d_in[2];
    const float* w1   = (const float*)d_in[3];
    const float* b1   = (const float*)d_in[4];
    const float* g1   = (const float*)d_in[5];
    const float* be1  = (const float*)d_in[6];
    const float* w2   = (const float*)d_in[7];
    const float* b2   = (const float*)d_in[8];
    const float* uw1  = (const float*)d_in[9];
    const float* ub1  = (const float*)d_in[10];
    const float* g2   = (const float*)d_in[11];
    const float* be2  = (const float*)d_in[12];
    const float* uw2  = (const float*)d_in[13];
    const float* ub2  = (const float*)d_in[14];
    float* out = (float*)d_out;

    float *dP, *dQ, *dR, *dW2p, *dH;
    cudaGetSymbolAddress((void**)&dP,   g_P);
    cudaGetSymbolAddress((void**)&dQ,   g_Q);
    cudaGetSymbolAddress((void**)&dR,   g_R);
    cudaGetSymbolAddress((void**)&dW2p, g_W2p);
    cudaGetSymbolAddress((void**)&dH,   g_H);

    zero_kernel<<<592, 256>>>();
    d2_kernel<<<1, 128>>>(uw1, b2);
    // W2p = W2 @ uw1b
    gemm128b<<<1, 256>>>(w2, 128, HD, uw1 + ND * HD, nullptr, nullptr, dW2p);
    // P = nf@W1a, Q = nf@W1b, R = ef@W1c + b1
    gemm128b<<<(N_NODES + 127) / 128, 256>>>(nf, N_NODES, ND, w1, nullptr, nullptr, dP);
    gemm128b<<<(N_NODES + 127) / 128, 256>>>(nf, N_NODES, ND, w1 + ND * HD, nullptr, nullptr, dQ);
    gemm128b<<<(E_EDGES + 127) / 128, 256>>>(ef, E_EDGES, ED, w1 + 2 * ND * HD, b1, nullptr, dR);
    // edges: gather + LN + scatter
    edge_kernel<<<(2 * E_EDGES) / 8, 256>>>(eidx, g1, be1);
    // update MLP
    upd1_kernel<<<(N_NODES + 127) / 128, 256>>>(nf, uw1, ub1, g2, be2);
    gemm128b<<<(N_NODES + 127) / 128, 256>>>(dH, N_NODES, HD, uw2, ub2, nf, out);
}

// round 5
// speedup vs baseline: 3.3802x; 1.1675x over previous
#include <cuda_runtime.h>
#include <math.h>

#define N_NODES 100000
#define E_EDGES 400000
#define ND 128
#define ED 64
#define HD 128
#define LN_EPS 1e-5f

typedef unsigned long long ull;

// Scratch (__device__ globals: allocation-free rule)
__device__ float g_hagg[(size_t)N_NODES * HD];
__device__ float g_deg[N_NODES];
__device__ float g_P[(size_t)N_NODES * HD];
__device__ float g_Q[(size_t)N_NODES * HD];
__device__ float g_R[(size_t)E_EDGES * HD];
__device__ float g_H[(size_t)N_NODES * HD];
__device__ float g_W2p[HD * HD];
__device__ float g_d2[HD];

// ---------------- packed f32x2 helpers ----------------
__device__ __forceinline__ void ffma2(ull& d, ull a, ull b) {
    asm("fma.rn.f32x2 %0, %1, %2, %0;" : "+l"(d) : "l"(a), "l"(b));
}
__device__ __forceinline__ ull pack2(float x, float y) {
    ull r; asm("mov.b64 %0, {%1, %2};" : "=l"(r) : "f"(x), "f"(y)); return r;
}
__device__ __forceinline__ ull pack2dup(float x) {
    ull r; asm("mov.b64 %0, {%1, %1};" : "=l"(r) : "f"(x)); return r;
}
__device__ __forceinline__ float2 unpack2(ull v) {
    float2 r; asm("mov.b64 {%0, %1}, %2;" : "=f"(r.x), "=f"(r.y) : "l"(v)); return r;
}
__device__ __forceinline__ void red_add_v4(float* p, float a, float b, float c, float d) {
    asm volatile("red.global.add.v4.f32 [%0], {%1, %2, %3, %4};"
                 :: "l"(p), "f"(a), "f"(b), "f"(c), "f"(d) : "memory");
}
__device__ __forceinline__ void red_add_f32(float* p, float v) {
    asm volatile("red.global.add.f32 [%0], %1;" :: "l"(p), "f"(v) : "memory");
}

__global__ void zero_kernel() {
    float4* p = reinterpret_cast<float4*>(g_hagg);
    const int n4 = N_NODES * HD / 4;
    for (int i = blockIdx.x * blockDim.x + threadIdx.x; i < n4;
         i += gridDim.x * blockDim.x)
        p[i] = make_float4(0.f, 0.f, 0.f, 0.f);
    for (int i = blockIdx.x * blockDim.x + threadIdx.x; i < N_NODES;
         i += gridDim.x * blockDim.x)
        g_deg[i] = 0.f;
}

__global__ void d2_kernel(const float* __restrict__ uw1, const float* __restrict__ b2) {
    int j = threadIdx.x;
    float s = 0.f;
    for (int k = 0; k < HD; k++)
        s = fmaf(b2[k], uw1[(ND + k) * HD + j], s);
    g_d2[j] = s;
}

// ---------------------------------------------------------------------------
// gemm128c: C[M][128] = A[M][K] @ W[K][128] (+bias)(+resid).
// 256 thr, 128 rows/block, 8x8 per-thread tile, FFMA2, X pre-dup'd in SMEM.
// ---------------------------------------------------------------------------
__global__ __launch_bounds__(256, 2) void gemm128c(
    const float* __restrict__ A, int M, int K,
    const float* __restrict__ W, const float* __restrict__ bias,
    const float* __restrict__ resid, float* __restrict__ C)
{
    __shared__ ull   Xd[16][136];   // dup'd X values, padded
    __shared__ float Ws[16][128];

    const int tid = threadIdx.x;
    const long rBase = (long)blockIdx.x * 128;
    const int trow = tid >> 4, tcol = tid & 15;
    const int r0 = trow * 8;
    const int lrA = tid >> 2, lqA = tid & 3;
    const int lkW = tid >> 5, lcW = tid & 31;
    long rowA0 = rBase + lrA;        if (rowA0 >= M) rowA0 = M - 1;
    long rowA1 = rBase + lrA + 64;   if (rowA1 >= M) rowA1 = M - 1;

    ull acc[8][4];
    {
        ull p0, p1, p2, p3;
        if (bias) {
            float4 b0 = *(const float4*)&bias[tcol * 4];
            float4 b1 = *(const float4*)&bias[tcol * 4 + 64];
            p0 = pack2(b0.x, b0.y); p1 = pack2(b0.z, b0.w);
            p2 = pack2(b1.x, b1.y); p3 = pack2(b1.z, b1.w);
        } else { p0 = p1 = p2 = p3 = 0ull; }
        #pragma unroll
        for (int i = 0; i < 8; i++) {
            acc[i][0] = p0; acc[i][1] = p1; acc[i][2] = p2; acc[i][3] = p3;
        }
    }

    for (int kc = 0; kc < K; kc += 16) {
        float4 x0 = *(const float4*)(A + rowA0 * K + kc + lqA * 4);
        float4 x1 = *(const float4*)(A + rowA1 * K + kc + lqA * 4);
        float4 w0 = *(const float4*)(W + (long)(kc + lkW) * 128 + lcW * 4);
        float4 w1 = *(const float4*)(W + (long)(kc + 8 + lkW) * 128 + lcW * 4);
        __syncthreads();
        {
            const float* xp0 = (const float*)&x0;
            const float* xp1 = (const float*)&x1;
            #pragma unroll
            for (int q = 0; q < 4; q++) {
                Xd[lqA * 4 + q][lrA]      = pack2dup(xp0[q]);
                Xd[lqA * 4 + q][lrA + 64] = pack2dup(xp1[q]);
            }
        }
        *(float4*)&Ws[lkW][lcW * 4]     = w0;
        *(float4*)&Ws[lkW + 8][lcW * 4] = w1;
        __syncthreads();
        #pragma unroll
        for (int k = 0; k < 16; k++) {
            ulonglong2 wv0 = *(const ulonglong2*)&Ws[k][tcol * 4];
            ulonglong2 wv1 = *(const ulonglong2*)&Ws[k][tcol * 4 + 64];
            #pragma unroll
            for (int i = 0; i < 8; i++) {
                ull xa = Xd[k][r0 + i];
                ffma2(acc[i][0], xa, wv0.x);
                ffma2(acc[i][1], xa, wv0.y);
                ffma2(acc[i][2], xa, wv1.x);
                ffma2(acc[i][3], xa, wv1.y);
            }
        }
    }

    #pragma unroll
    for (int i = 0; i < 8; i++) {
        long row = rBase + r0 + i;
        if (row < M) {
            float2 a0 = unpack2(acc[i][0]), a1 = unpack2(acc[i][1]);
            float2 a2 = unpack2(acc[i][2]), a3 = unpack2(acc[i][3]);
            float4 v0 = make_float4(a0.x, a0.y, a1.x, a1.y);
            float4 v1 = make_float4(a2.x, a2.y, a3.x, a3.y);
            int c = tcol * 4;
            if (resid) {
                float4 n0 = *(const float4*)(resid + row * 128 + c);
                float4 n1 = *(const float4*)(resid + row * 128 + c + 64);
                v0.x += n0.x; v0.y += n0.y; v0.z += n0.z; v0.w += n0.w;
                v1.x += n1.x; v1.y += n1.y; v1.z += n1.z; v1.w += n1.w;
            }
            *(float4*)(C + row * 128 + c)      = v0;
            *(float4*)(C + row * 128 + c + 64) = v1;
        }
    }
}

// ---------------------------------------------------------------------------
// Edge kernel: one warp per UNDIRECTED edge; computes both directions.
//   fwd: h = relu(LN(P[s]+Q[t]+R[e])) -> hagg[t]
//   bwd: h = relu(LN(P[t]+Q[s]+R[e])) -> hagg[s]
// ---------------------------------------------------------------------------
__global__ __launch_bounds__(256) void edge_kernel(
    const int* __restrict__ eidx,
    const float* __restrict__ g1, const float* __restrict__ be1)
{
    const int wid = threadIdx.x >> 5, lane = threadIdx.x & 31;
    const long e = (long)blockIdx.x * 8 + wid;
    const int s = eidx[e], t = eidx[E_EDGES + e];

    float4 ps = *(const float4*)(g_P + (long)s * HD + lane * 4);
    float4 pt = *(const float4*)(g_P + (long)t * HD + lane * 4);
    float4 qs = *(const float4*)(g_Q + (long)s * HD + lane * 4);
    float4 qt = *(const float4*)(g_Q + (long)t * HD + lane * 4);
    float4 r  = *(const float4*)(g_R + e * HD + lane * 4);
    float4 gg = *(const float4*)&g1[lane * 4];
    float4 bb = *(const float4*)&be1[lane * 4];

    float4 vf = make_float4(ps.x + qt.x + r.x, ps.y + qt.y + r.y,
                            ps.z + qt.z + r.z, ps.w + qt.w + r.w);
    float4 vb = make_float4(pt.x + qs.x + r.x, pt.y + qs.y + r.y,
                            pt.z + qs.z + r.z, pt.w + qs.w + r.w);

    float s1f = vf.x + vf.y + vf.z + vf.w;
    float ssf = vf.x * vf.x + vf.y * vf.y + vf.z * vf.z + vf.w * vf.w;
    float s1b = vb.x + vb.y + vb.z + vb.w;
    float ssb = vb.x * vb.x + vb.y * vb.y + vb.z * vb.z + vb.w * vb.w;
    #pragma unroll
    for (int o = 16; o >= 1; o >>= 1) {
        s1f += __shfl_xor_sync(0xffffffffu, s1f, o);
        ssf += __shfl_xor_sync(0xffffffffu, ssf, o);
        s1b += __shfl_xor_sync(0xffffffffu, s1b, o);
        ssb += __shfl_xor_sync(0xffffffffu, ssb, o);
    }
    {
        float mean = s1f * (1.0f / HD);
        float var  = ssf * (1.0f / HD) - mean * mean;
        float rstd = rsqrtf(var + LN_EPS);
        float h0 = fmaxf((vf.x - mean) * rstd * gg.x + bb.x, 0.f);
        float h1 = fmaxf((vf.y - mean) * rstd * gg.y + bb.y, 0.f);
        float h2 = fmaxf((vf.z - mean) * rstd * gg.z + bb.z, 0.f);
        float h3 = fmaxf((vf.w - mean) * rstd * gg.w + bb.w, 0.f);
        red_add_v4(g_hagg + (long)t * HD + lane * 4, h0, h1, h2, h3);
    }
    {
        float mean = s1b * (1.0f / HD);
        float var  = ssb * (1.0f / HD) - mean * mean;
        float rstd = rsqrtf(var + LN_EPS);
        float h0 = fmaxf((vb.x - mean) * rstd * gg.x + bb.x, 0.f);
        float h1 = fmaxf((vb.y - mean) * rstd * gg.y + bb.y, 0.f);
        float h2 = fmaxf((vb.z - mean) * rstd * gg.z + bb.z, 0.f);
        float h3 = fmaxf((vb.w - mean) * rstd * gg.w + bb.w, 0.f);
        red_add_v4(g_hagg + (long)s * HD + lane * 4, h0, h1, h2, h3);
    }
    if (lane == 0) { red_add_f32(g_deg + t, 1.0f); red_add_f32(g_deg + s, 1.0f); }
}

// ---------------------------------------------------------------------------
// upd1: T = nf@uw1a + hagg@W2p + deg*d2 + ub1; g_H = relu(LN(T))
// ---------------------------------------------------------------------------
__global__ __launch_bounds__(256, 2) void upd1_kernel(
    const float* __restrict__ nf, const float* __restrict__ uw1,
    const float* __restrict__ ub1,
    const float* __restrict__ g2, const float* __restrict__ be2)
{
    __shared__ ull   Xd[16][136];
    __shared__ float Ws[16][128];

    const int tid = threadIdx.x;
    const long rBase = (long)blockIdx.x * 128;
    const int trow = tid >> 4, tcol = tid & 15;
    const int r0 = trow * 8;
    const int lrA = tid >> 2, lqA = tid & 3;
    const int lkW = tid >> 5, lcW = tid & 31;
    long rowA0 = rBase + lrA;        if (rowA0 >= N_NODES) rowA0 = N_NODES - 1;
    long rowA1 = rBase + lrA + 64;   if (rowA1 >= N_NODES) rowA1 = N_NODES - 1;

    ull acc[8][4];
    {
        float4 b0 = *(const float4*)&ub1[tcol * 4];
        float4 b1 = *(const float4*)&ub1[tcol * 4 + 64];
        ull p0 = pack2(b0.x, b0.y), p1 = pack2(b0.z, b0.w);
        ull p2 = pack2(b1.x, b1.y), p3 = pack2(b1.z, b1.w);
        #pragma unroll
        for (int i = 0; i < 8; i++) {
            acc[i][0] = p0; acc[i][1] = p1; acc[i][2] = p2; acc[i][3] = p3;
        }
    }

    #pragma unroll 1
    for (int seg = 0; seg < 2; seg++) {
        const float* A = seg ? g_hagg : nf;
        const float* W = seg ? g_W2p : uw1;
        for (int kc = 0; kc < HD; kc += 16) {
            float4 x0 = *(const float4*)(A + rowA0 * HD + kc + lqA * 4);
            float4 x1 = *(const float4*)(A + rowA1 * HD + kc + lqA * 4);
            float4 w0 = *(const float4*)(W + (long)(kc + lkW) * 128 + lcW * 4);
            float4 w1 = *(const float4*)(W + (long)(kc + 8 + lkW) * 128 + lcW * 4);
            __syncthreads();
            {
                const float* xp0 = (const float*)&x0;
                const float* xp1 = (const float*)&x1;
                #pragma unroll
                for (int q = 0; q < 4; q++) {
                    Xd[lqA * 4 + q][lrA]      = pack2dup(xp0[q]);
                    Xd[lqA * 4 + q][lrA + 64] = pack2dup(xp1[q]);
                }
            }
            *(float4*)&Ws[lkW][lcW * 4]     = w0;
            *(float4*)&Ws[lkW + 8][lcW * 4] = w1;
            __syncthreads();
            #pragma unroll
            for (int k = 0; k < 16; k++) {
                ulonglong2 wv0 = *(const ulonglong2*)&Ws[k][tcol * 4];
                ulonglong2 wv1 = *(const ulonglong2*)&Ws[k][tcol * 4 + 64];
                #pragma unroll
                for (int i = 0; i < 8; i++) {
                    ull xa = Xd[k][r0 + i];
                    ffma2(acc[i][0], xa, wv0.x);
                    ffma2(acc[i][1], xa, wv0.y);
                    ffma2(acc[i][2], xa, wv1.x);
                    ffma2(acc[i][3], xa, wv1.y);
                }
            }
        }
    }

    float4 d20 = *(const float4*)&g_d2[tcol * 4];
    float4 d21 = *(const float4*)&g_d2[tcol * 4 + 64];
    float4 gg0 = *(const float4*)&g2[tcol * 4];
    float4 gg1 = *(const float4*)&g2[tcol * 4 + 64];
    float4 bb0 = *(const float4*)&be2[tcol * 4];
    float4 bb1 = *(const float4*)&be2[tcol * 4 + 64];

    #pragma unroll
    for (int i = 0; i < 8; i++) {
        long row = rBase + r0 + i;
        long rowc = row < N_NODES ? row : N_NODES - 1;
        float dg = g_deg[rowc];
        float2 a0 = unpack2(acc[i][0]), a1 = unpack2(acc[i][1]);
        float2 a2 = unpack2(acc[i][2]), a3 = unpack2(acc[i][3]);
        float va[8];
        va[0] = a0.x + dg * d20.x; va[1] = a0.y + dg * d20.y;
        va[2] = a1.x + dg * d20.z; va[3] = a1.y + dg * d20.w;
        va[4] = a2.x + dg * d21.x; va[5] = a2.y + dg * d21.y;
        va[6] = a3.x + dg * d21.z; va[7] = a3.y + dg * d21.w;
        float s = 0.f, ss = 0.f;
        #pragma unroll
        for (int j = 0; j < 8; j++) { s += va[j]; ss += va[j] * va[j]; }
        #pragma unroll
        for (int o = 8; o >= 1; o >>= 1) {
            s  += __shfl_xor_sync(0xffffffffu, s,  o);
            ss += __shfl_xor_sync(0xffffffffu, ss, o);
        }
        float mean = s * (1.0f / HD);
        float var  = ss * (1.0f / HD) - mean * mean;
        float rstd = rsqrtf(var + LN_EPS);
        if (row < N_NODES) {
            float4 h0, h1;
            h0.x = fmaxf((va[0] - mean) * rstd * gg0.x + bb0.x, 0.f);
            h0.y = fmaxf((va[1] - mean) * rstd * gg0.y + bb0.y, 0.f);
            h0.z = fmaxf((va[2] - mean) * rstd * gg0.z + bb0.z, 0.f);
            h0.w = fmaxf((va[3] - mean) * rstd * gg0.w + bb0.w, 0.f);
            h1.x = fmaxf((va[4] - mean) * rstd * gg1.x + bb1.x, 0.f);
            h1.y = fmaxf((va[5] - mean) * rstd * gg1.y + bb1.y, 0.f);
            h1.z = fmaxf((va[6] - mean) * rstd * gg1.z + bb1.z, 0.f);
            h1.w = fmaxf((va[7] - mean) * rstd * gg1.w + bb1.w, 0.f);
            *(float4*)(g_H + row * HD + tcol * 4)      = h0;
            *(float4*)(g_H + row * HD + tcol * 4 + 64) = h1;
        }
    }
}

extern "C" void kernel_launch(void* const* d_in, const int* in_sizes, int n_in,
                              void* d_out, int out_size)
{
    const float* nf   = (const float*)d_in[0];
    const float* ef   = (const float*)d_in[1];
    const int*   eidx = (const int*)  d_in[2];
    const float* w1   = (const float*)d_in[3];
    const float* b1   = (const float*)d_in[4];
    const float* g1   = (const float*)d_in[5];
    const float* be1  = (const float*)d_in[6];
    const float* w2   = (const float*)d_in[7];
    const float* b2   = (const float*)d_in[8];
    const float* uw1  = (const float*)d_in[9];
    const float* ub1  = (const float*)d_in[10];
    const float* g2   = (const float*)d_in[11];
    const float* be2  = (const float*)d_in[12];
    const float* uw2  = (const float*)d_in[13];
    const float* ub2  = (const float*)d_in[14];
    float* out = (float*)d_out;

    float *dP, *dQ, *dR, *dW2p, *dH;
    cudaGetSymbolAddress((void**)&dP,   g_P);
    cudaGetSymbolAddress((void**)&dQ,   g_Q);
    cudaGetSymbolAddress((void**)&dR,   g_R);
    cudaGetSymbolAddress((void**)&dW2p, g_W2p);
    cudaGetSymbolAddress((void**)&dH,   g_H);

    zero_kernel<<<592, 256>>>();
    d2_kernel<<<1, 128>>>(uw1, b2);
    gemm128c<<<1, 256>>>(w2, 128, HD, uw1 + ND * HD, nullptr, nullptr, dW2p);
    gemm128c<<<(N_NODES + 127) / 128, 256>>>(nf, N_NODES, ND, w1, nullptr, nullptr, dP);
    gemm128c<<<(N_NODES + 127) / 128, 256>>>(nf, N_NODES, ND, w1 + ND * HD, nullptr, nullptr, dQ);
    gemm128c<<<(E_EDGES + 127) / 128, 256>>>(ef, E_EDGES, ED, w1 + 2 * ND * HD, b1, nullptr, dR);
    edge_kernel<<<E_EDGES / 8, 256>>>(eidx, g1, be1);
    upd1_kernel<<<(N_NODES + 127) / 128, 256>>>(nf, uw1, ub1, g2, be2);
    gemm128c<<<(N_NODES + 127) / 128, 256>>>(dH, N_NODES, HD, uw2, ub2, nf, out);
}

// round 6
// speedup vs baseline: 3.9213x; 1.1601x over previous
#include <cuda_runtime.h>
#include <math.h>
#include <stdint.h>

#define N_NODES 100000
#define E_EDGES 400000
#define ND 128
#define ED 64
#define HD 128
#define LN_EPS 1e-5f

typedef unsigned long long ull;

// Scratch (__device__ globals: allocation-free rule)
__device__ float g_hagg[(size_t)N_NODES * HD];
__device__ float g_deg[N_NODES];
__device__ float g_P[(size_t)N_NODES * HD];
__device__ float g_Q[(size_t)N_NODES * HD];
__device__ float g_R[(size_t)E_EDGES * HD];
__device__ float g_T[(size_t)N_NODES * HD];
__device__ float g_H[(size_t)N_NODES * HD];
__device__ float g_W2p[HD * HD];
__device__ float g_d2[HD];

// ---------------- helpers ----------------
__device__ __forceinline__ void red_add_v4(float* p, float a, float b, float c, float d) {
    asm volatile("red.global.add.v4.f32 [%0], {%1, %2, %3, %4};"
                 :: "l"(p), "f"(a), "f"(b), "f"(c), "f"(d) : "memory");
}
__device__ __forceinline__ void red_add_f32(float* p, float v) {
    asm volatile("red.global.add.f32 [%0], %1;" :: "l"(p), "f"(v) : "memory");
}
__device__ __forceinline__ void split_tf32(float x, uint32_t& hi, uint32_t& lo) {
    asm("cvt.rna.tf32.f32 %0, %1;" : "=r"(hi) : "f"(x));
    float r = x - __uint_as_float(hi);
    asm("cvt.rna.tf32.f32 %0, %1;" : "=r"(lo) : "f"(r));
}
__device__ __forceinline__ void mma_tf32(float d[4], const uint32_t a[4], const uint32_t b[2]) {
    asm("mma.sync.aligned.m16n8k8.row.col.f32.tf32.tf32.f32 "
        "{%0,%1,%2,%3}, {%4,%5,%6,%7}, {%8,%9}, {%0,%1,%2,%3};"
        : "+f"(d[0]), "+f"(d[1]), "+f"(d[2]), "+f"(d[3])
        : "r"(a[0]), "r"(a[1]), "r"(a[2]), "r"(a[3]), "r"(b[0]), "r"(b[1]));
}
__device__ __forceinline__ void cp_async16(void* smem, const void* gmem) {
    uint32_t s = (uint32_t)__cvta_generic_to_shared(smem);
    asm volatile("cp.async.cg.shared.global [%0], [%1], 16;" :: "r"(s), "l"(gmem));
}
#define CP_COMMIT() asm volatile("cp.async.commit_group;")
#define CP_WAIT1()  asm volatile("cp.async.wait_group 1;")

__global__ void zero_kernel() {
    float4* p = reinterpret_cast<float4*>(g_hagg);
    const int n4 = N_NODES * HD / 4;
    for (int i = blockIdx.x * blockDim.x + threadIdx.x; i < n4;
         i += gridDim.x * blockDim.x)
        p[i] = make_float4(0.f, 0.f, 0.f, 0.f);
    for (int i = blockIdx.x * blockDim.x + threadIdx.x; i < N_NODES;
         i += gridDim.x * blockDim.x)
        g_deg[i] = 0.f;
}

__global__ void d2_kernel(const float* __restrict__ uw1, const float* __restrict__ b2) {
    int j = threadIdx.x;
    float s = 0.f;
    for (int k = 0; k < HD; k++)
        s = fmaf(b2[k], uw1[(ND + k) * HD + j], s);
    g_d2[j] = s;
}

// ---------------------------------------------------------------------------
// gemm_tc: C[M][128] = A[M][K] @ W[K][128] (+bias)(+C if addC)(+resid).
// 3xTF32 mma.sync, BM=64/BN=128/BK=16, 256 thr (8 warps 2x4, warp tile 32x32),
// cp.async double-buffered.
// ---------------------------------------------------------------------------
__global__ __launch_bounds__(256, 2) void gemm_tc(
    const float* __restrict__ A, int M, int K,
    const float* __restrict__ W, const float* __restrict__ bias,
    const float* __restrict__ resid, int addC, float* __restrict__ C)
{
    __shared__ float As[2][64][20];    // [m][k] row-major, pad 20 (80B, 16B-mult)
    __shared__ float Ws[2][16][136];   // [k][n], pad 136 (544B, 16B-mult)

    const int tid = threadIdx.x;
    const int lane = tid & 31, warp = tid >> 5;
    const int wm = warp >> 2, wn = warp & 3;   // 2 x 4 warp grid
    const int g = lane >> 2, tig = lane & 3;
    const long rBase = (long)blockIdx.x * 64;

    // loader mapping
    const int arow = tid >> 2, akq = tid & 3;  // A: 64 rows x 4 quads
    long gArow = rBase + arow; if (gArow >= M) gArow = M - 1;
    const int wkr = tid >> 5, wcc = tid & 31;  // W: rows wkr, wkr+8; col quad wcc

    const int nChunks = K >> 4;

    float d[2][4][4];
    #pragma unroll
    for (int mf = 0; mf < 2; mf++)
        #pragma unroll
        for (int nf = 0; nf < 4; nf++)
            #pragma unroll
            for (int q = 0; q < 4; q++) d[mf][nf][q] = 0.f;

    // prologue: chunk 0
    cp_async16(&As[0][arow][akq * 4], A + gArow * K + akq * 4);
    cp_async16(&Ws[0][wkr][wcc * 4],     W + (long)wkr * 128 + wcc * 4);
    cp_async16(&Ws[0][wkr + 8][wcc * 4], W + (long)(wkr + 8) * 128 + wcc * 4);
    CP_COMMIT();

    for (int c = 0; c < nChunks; c++) {
        if (c + 1 < nChunks) {
            int kc = (c + 1) * 16, buf = (c + 1) & 1;
            cp_async16(&As[buf][arow][akq * 4], A + gArow * K + kc + akq * 4);
            cp_async16(&Ws[buf][wkr][wcc * 4],     W + (long)(kc + wkr) * 128 + wcc * 4);
            cp_async16(&Ws[buf][wkr + 8][wcc * 4], W + (long)(kc + 8 + wkr) * 128 + wcc * 4);
        }
        CP_COMMIT();
        CP_WAIT1();
        __syncthreads();
        const int buf = c & 1;
        #pragma unroll
        for (int k8 = 0; k8 < 16; k8 += 8) {
            uint32_t ahi[2][4], alo[2][4], bhi[4][2], blo[4][2];
            #pragma unroll
            for (int mf = 0; mf < 2; mf++) {
                int mb = wm * 32 + mf * 16;
                split_tf32(As[buf][mb + g][k8 + tig],         ahi[mf][0], alo[mf][0]);
                split_tf32(As[buf][mb + 8 + g][k8 + tig],     ahi[mf][1], alo[mf][1]);
                split_tf32(As[buf][mb + g][k8 + tig + 4],     ahi[mf][2], alo[mf][2]);
                split_tf32(As[buf][mb + 8 + g][k8 + tig + 4], ahi[mf][3], alo[mf][3]);
            }
            #pragma unroll
            for (int nf = 0; nf < 4; nf++) {
                int nb = wn * 32 + nf * 8;
                split_tf32(Ws[buf][k8 + tig][nb + g],     bhi[nf][0], blo[nf][0]);
                split_tf32(Ws[buf][k8 + tig + 4][nb + g], bhi[nf][1], blo[nf][1]);
            }
            #pragma unroll
            for (int mf = 0; mf < 2; mf++)
                #pragma unroll
                for (int nf = 0; nf < 4; nf++) {
                    mma_tf32(d[mf][nf], ahi[mf], bhi[nf]);
                    mma_tf32(d[mf][nf], alo[mf], bhi[nf]);
                    mma_tf32(d[mf][nf], ahi[mf], blo[nf]);
                }
        }
        __syncthreads();   // all reads of buf done before it is refilled
    }

    // epilogue
    #pragma unroll
    for (int mf = 0; mf < 2; mf++) {
        #pragma unroll
        for (int r2 = 0; r2 < 2; r2++) {
            long m = rBase + wm * 32 + mf * 16 + g + r2 * 8;
            if (m < M) {
                #pragma unroll
                for (int nf = 0; nf < 4; nf++) {
                    int n = wn * 32 + nf * 8 + 2 * tig;
                    float v0 = d[mf][nf][r2 * 2];
                    float v1 = d[mf][nf][r2 * 2 + 1];
                    if (bias)  { v0 += bias[n];  v1 += bias[n + 1]; }
                    if (addC)  { float2 cc = *(const float2*)(C + m * 128 + n);
                                 v0 += cc.x; v1 += cc.y; }
                    if (resid) { float2 rr = *(const float2*)(resid + m * 128 + n);
                                 v0 += rr.x; v1 += rr.y; }
                    *(float2*)(C + m * 128 + n) = make_float2(v0, v1);
                }
            }
        }
    }
}

// ---------------------------------------------------------------------------
// Edge kernel: one warp per UNDIRECTED edge; both directions.
// ---------------------------------------------------------------------------
__global__ __launch_bounds__(256) void edge_kernel(
    const int* __restrict__ eidx,
    const float* __restrict__ g1, const float* __restrict__ be1)
{
    const int wid = threadIdx.x >> 5, lane = threadIdx.x & 31;
    const long e = (long)blockIdx.x * 8 + wid;
    const int s = eidx[e], t = eidx[E_EDGES + e];

    float4 ps = *(const float4*)(g_P + (long)s * HD + lane * 4);
    float4 pt = *(const float4*)(g_P + (long)t * HD + lane * 4);
    float4 qs = *(const float4*)(g_Q + (long)s * HD + lane * 4);
    float4 qt = *(const float4*)(g_Q + (long)t * HD + lane * 4);
    float4 r  = *(const float4*)(g_R + e * HD + lane * 4);
    float4 gg = *(const float4*)&g1[lane * 4];
    float4 bb = *(const float4*)&be1[lane * 4];

    float4 vf = make_float4(ps.x + qt.x + r.x, ps.y + qt.y + r.y,
                            ps.z + qt.z + r.z, ps.w + qt.w + r.w);
    float4 vb = make_float4(pt.x + qs.x + r.x, pt.y + qs.y + r.y,
                            pt.z + qs.z + r.z, pt.w + qs.w + r.w);

    float s1f = vf.x + vf.y + vf.z + vf.w;
    float ssf = vf.x * vf.x + vf.y * vf.y + vf.z * vf.z + vf.w * vf.w;
    float s1b = vb.x + vb.y + vb.z + vb.w;
    float ssb = vb.x * vb.x + vb.y * vb.y + vb.z * vb.z + vb.w * vb.w;
    #pragma unroll
    for (int o = 16; o >= 1; o >>= 1) {
        s1f += __shfl_xor_sync(0xffffffffu, s1f, o);
        ssf += __shfl_xor_sync(0xffffffffu, ssf, o);
        s1b += __shfl_xor_sync(0xffffffffu, s1b, o);
        ssb += __shfl_xor_sync(0xffffffffu, ssb, o);
    }
    {
        float mean = s1f * (1.0f / HD);
        float var  = ssf * (1.0f / HD) - mean * mean;
        float rstd = rsqrtf(var + LN_EPS);
        float h0 = fmaxf((vf.x - mean) * rstd * gg.x + bb.x, 0.f);
        float h1 = fmaxf((vf.y - mean) * rstd * gg.y + bb.y, 0.f);
        float h2 = fmaxf((vf.z - mean) * rstd * gg.z + bb.z, 0.f);
        float h3 = fmaxf((vf.w - mean) * rstd * gg.w + bb.w, 0.f);
        red_add_v4(g_hagg + (long)t * HD + lane * 4, h0, h1, h2, h3);
    }
    {
        float mean = s1b * (1.0f / HD);
        float var  = ssb * (1.0f / HD) - mean * mean;
        float rstd = rsqrtf(var + LN_EPS);
        float h0 = fmaxf((vb.x - mean) * rstd * gg.x + bb.x, 0.f);
        float h1 = fmaxf((vb.y - mean) * rstd * gg.y + bb.y, 0.f);
        float h2 = fmaxf((vb.z - mean) * rstd * gg.z + bb.z, 0.f);
        float h3 = fmaxf((vb.w - mean) * rstd * gg.w + bb.w, 0.f);
        red_add_v4(g_hagg + (long)s * HD + lane * 4, h0, h1, h2, h3);
    }
    if (lane == 0) { red_add_f32(g_deg + t, 1.0f); red_add_f32(g_deg + s, 1.0f); }
}

// ---------------------------------------------------------------------------
// ln2: g_H = relu(LN(g_T + deg*d2) * g2 + be2).  One warp per node row.
// ---------------------------------------------------------------------------
__global__ __launch_bounds__(256) void ln2_kernel(
    const float* __restrict__ g2, const float* __restrict__ be2)
{
    const int row = blockIdx.x * 8 + (threadIdx.x >> 5);
    const int lane = threadIdx.x & 31;
    if (row >= N_NODES) return;
    float4 v = *(const float4*)(g_T + (long)row * HD + lane * 4);
    float dg = g_deg[row];
    float4 dd = *(const float4*)&g_d2[lane * 4];
    v.x += dg * dd.x; v.y += dg * dd.y; v.z += dg * dd.z; v.w += dg * dd.w;
    float s1 = v.x + v.y + v.z + v.w;
    float ss = v.x * v.x + v.y * v.y + v.z * v.z + v.w * v.w;
    #pragma unroll
    for (int o = 16; o >= 1; o >>= 1) {
        s1 += __shfl_xor_sync(0xffffffffu, s1, o);
        ss += __shfl_xor_sync(0xffffffffu, ss, o);
    }
    float mean = s1 * (1.0f / HD);
    float var  = ss * (1.0f / HD) - mean * mean;
    float rstd = rsqrtf(var + LN_EPS);
    float4 gg = *(const float4*)&g2[lane * 4];
    float4 bb = *(const float4*)&be2[lane * 4];
    float4 h;
    h.x = fmaxf((v.x - mean) * rstd * gg.x + bb.x, 0.f);
    h.y = fmaxf((v.y - mean) * rstd * gg.y + bb.y, 0.f);
    h.z = fmaxf((v.z - mean) * rstd * gg.z + bb.z, 0.f);
    h.w = fmaxf((v.w - mean) * rstd * gg.w + bb.w, 0.f);
    *(float4*)(g_H + (long)row * HD + lane * 4) = h;
}

extern "C" void kernel_launch(void* const* d_in, const int* in_sizes, int n_in,
                              void* d_out, int out_size)
{
    const float* nf   = (const float*)d_in[0];
    const float* ef   = (const float*)d_in[1];
    const int*   eidx = (const int*)  d_in[2];
    const float* w1   = (const float*)d_in[3];
    const float* b1   = (const float*)d_in[4];
    const float* g1   = (const float*)d_in[5];
    const float* be1  = (const float*)d_in[6];
    const float* w2   = (const float*)d_in[7];
    const float* b2   = (const float*)d_in[8];
    const float* uw1  = (const float*)d_in[9];
    const float* ub1  = (const float*)d_in[10];
    const float* g2   = (const float*)d_in[11];
    const float* be2  = (const float*)d_in[12];
    const float* uw2  = (const float*)d_in[13];
    const float* ub2  = (const float*)d_in[14];
    float* out = (float*)d_out;

    float *dP, *dQ, *dR, *dT, *dH, *dW2p, *dHagg;
    cudaGetSymbolAddress((void**)&dP,    g_P);
    cudaGetSymbolAddress((void**)&dQ,    g_Q);
    cudaGetSymbolAddress((void**)&dR,    g_R);
    cudaGetSymbolAddress((void**)&dT,    g_T);
    cudaGetSymbolAddress((void**)&dH,    g_H);
    cudaGetSymbolAddress((void**)&dW2p,  g_W2p);
    cudaGetSymbolAddress((void**)&dHagg, g_hagg);

    const int gN = (N_NODES + 63) / 64;   // 1563
    const int gE = E_EDGES / 64;          // 6250

    zero_kernel<<<592, 256>>>();
    d2_kernel<<<1, 128>>>(uw1, b2);
    // W2p = W2 @ uw1b
    gemm_tc<<<2, 256>>>(w2, 128, HD, uw1 + ND * HD, nullptr, nullptr, 0, dW2p);
    // P = nf@W1a, Q = nf@W1b, R = ef@W1c + b1
    gemm_tc<<<gN, 256>>>(nf, N_NODES, ND, w1, nullptr, nullptr, 0, dP);
    gemm_tc<<<gN, 256>>>(nf, N_NODES, ND, w1 + ND * HD, nullptr, nullptr, 0, dQ);
    gemm_tc<<<gE, 256>>>(ef, E_EDGES, ED, w1 + 2 * ND * HD, b1, nullptr, 0, dR);
    // edges: gather + LN + scatter
    edge_kernel<<<E_EDGES / 8, 256>>>(eidx, g1, be1);
    // update MLP: T = nf@uw1a + ub1; T += hagg@W2p; H = relu(LN(T + deg*d2))
    gemm_tc<<<gN, 256>>>(nf, N_NODES, ND, uw1, ub1, nullptr, 0, dT);
    gemm_tc<<<gN, 256>>>(dHagg, N_NODES, HD, dW2p, nullptr, nullptr, 1, dT);
    ln2_kernel<<<(N_NODES + 7) / 8, 256>>>(g2, be2);
    // out = H@uw2 + ub2 + nf
    gemm_tc<<<gN, 256>>>(dH, N_NODES, HD, uw2, ub2, nf, 0, out);
}